// round 14
// baseline (speedup 1.0000x reference)
#include <cuda_runtime.h>
#include <math.h>
#include <stdint.h>

#define BSZ 16
#define NA  8400
#define NM  64
#define NC  80
#define KTOP 10
#define EPS9 1e-9f

#define NBX   16
#define NBINS 256          // 16x16 bins of 40px over 640x640
#define INV_BINW 0.025f    // 1/40
#define MAXC  1024

#define ZBLK 525           // blocks that init scratch (g_cnt etc.)

// ---------------- scratch (__device__ globals; allowed) ----------------
__device__ int      g_cnt[BSZ * NA];
__device__ int      g_m[BSZ * NA];
__device__ float    g_al[BSZ * NA];
__device__ float    g_ov[BSZ * NA];
__device__ int      g_lbl[BSZ * NA];     // final label, -1 = background
__device__ int      g_tgt[BSZ * NA];
__device__ float    g_fin[BSZ * NA];
__device__ unsigned g_pos_al[BSZ * NM];
__device__ unsigned g_pos_ov[BSZ * NM];
// binning
__device__ float2   g_bxy[NA];
__device__ int      g_bidx[NA];
__device__ int      g_bs[NBINS + 1];

// ---------------- helpers ----------------
static __device__ __forceinline__ float ciou_f(float4 g, float4 p) {
    const float eps = 1e-7f;
    float w1 = g.z - g.x, h1 = g.w - g.y;
    float w2 = p.z - p.x, h2 = p.w - p.y;
    float iw = fmaxf(fminf(g.z, p.z) - fmaxf(g.x, p.x), 0.0f);
    float ih = fmaxf(fminf(g.w, p.w) - fmaxf(g.y, p.y), 0.0f);
    float inter = iw * ih;
    float uni = w1 * h1 + w2 * h2 - inter + eps;
    float iou = inter / uni;
    float cw = fmaxf(g.z, p.z) - fminf(g.x, p.x);
    float ch = fmaxf(g.w, p.w) - fminf(g.y, p.y);
    float c2 = cw * cw + ch * ch + eps;
    float dx = p.x + p.z - g.x - g.z;
    float dy = p.y + p.w - g.y - g.w;
    float rho2 = (dx * dx + dy * dy) * 0.25f;
    float d = atanf(w1 / (h1 + eps)) - atanf(w2 / (h2 + eps));
    float v = 0.4052847345693511f * d * d;   // 4/pi^2
    float alpha = v / (v - iou + 1.0f + eps);
    return iou - (rho2 / c2 + v * alpha);
}

static __device__ __forceinline__ bool inside_box(float2 a, float4 g) {
    float m0 = fminf(a.x - g.x, a.y - g.y);
    float m1 = fminf(g.z - a.x, g.w - a.y);
    return fminf(m0, m1) > EPS9;
}

// ---------------- K0: init scratch + bin anchors (fused, small) -----------
__global__ void __launch_bounds__(256) k_prep(const float* __restrict__ anc) {
    int tid = threadIdx.x;

    if (blockIdx.x == ZBLK) {
        __shared__ int cnt[NBINS];
        __shared__ int ofs[NBINS];
        __shared__ int scn[NBINS];
        cnt[tid] = 0;
        __syncthreads();
        for (int a = tid; a < NA; a += 256) {
            float2 an = ((const float2*)anc)[a];
            int bx = min(max((int)(an.x * INV_BINW), 0), NBX - 1);
            int by = min(max((int)(an.y * INV_BINW), 0), NBX - 1);
            atomicAdd(&cnt[by * NBX + bx], 1);
        }
        __syncthreads();
        int x = cnt[tid];
        scn[tid] = x;
        __syncthreads();
#pragma unroll
        for (int d = 1; d < NBINS; d <<= 1) {
            int v = (tid >= d) ? scn[tid - d] : 0;
            __syncthreads();
            scn[tid] += v;
            __syncthreads();
        }
        int excl = scn[tid] - x;
        ofs[tid] = excl;
        g_bs[tid] = excl;
        if (tid == NBINS - 1) g_bs[NBINS] = scn[tid];
        __syncthreads();
        for (int a = tid; a < NA; a += 256) {
            float2 an = ((const float2*)anc)[a];
            int bx = min(max((int)(an.x * INV_BINW), 0), NBX - 1);
            int by = min(max((int)(an.y * INV_BINW), 0), NBX - 1);
            int p = atomicAdd(&ofs[by * NBX + bx], 1);
            g_bxy[p] = an;
            g_bidx[p] = a;
        }
        return;
    }

    int t = blockIdx.x * 256 + tid;
    if (t < BSZ * NA) g_cnt[t] = 0;
    if (t < BSZ * NM) { g_pos_al[t] = 0u; g_pos_ov[t] = 0u; }
}

// ---------------- K1: per (b,m) binned scan + rank top-10 (early exit) ----
__global__ void __launch_bounds__(128) k_phaseA(
    const float* __restrict__ pd_scores, const float* __restrict__ pd_bboxes,
    const float* __restrict__ anc, const int* __restrict__ gt_labels,
    const float* __restrict__ gt_bboxes)
{
    int bm = blockIdx.x;
    int b = bm >> 6;
    int tid = threadIdx.x;

    __shared__ unsigned long long s_key[MAXC];  // (vbits<<32)|(0x7FFFFFFF - idx)
    __shared__ float s_ovs[MAXC];
    __shared__ int   s_ia[MAXC];
    __shared__ int   s_n;
    if (tid == 0) s_n = 0;

    float4 g = __ldg((const float4*)gt_bboxes + bm);
    int lbl = __ldg(gt_labels + bm);
    const float* sc = pd_scores + (size_t)b * NA * NC + lbl;
    const float4* pb = (const float4*)pd_bboxes + (size_t)b * NA;
    __syncthreads();

    int bx0 = min(max((int)(g.x * INV_BINW), 0), NBX - 1);
    int bx1 = min(max((int)(g.z * INV_BINW), 0), NBX - 1);
    int by0 = min(max((int)(g.y * INV_BINW), 0), NBX - 1);
    int by1 = min(max((int)(g.w * INV_BINW), 0), NBX - 1);

    for (int by = by0; by <= by1; by++) {
        int j0 = g_bs[by * NBX + bx0];
        int j1 = g_bs[by * NBX + bx1 + 1];
        for (int j = j0 + tid; j < j1; j += 128) {
            float2 an = g_bxy[j];
            if (!inside_box(an, g)) continue;
            int a = g_bidx[j];
            float4 p = __ldg(pb + a);
            float ov = fmaxf(ciou_f(g, p), 0.0f);
            if (ov <= 0.0f) continue;
            float s = __ldg(sc + (size_t)a * NC);
            float o2 = ov * ov;
            float v = sqrtf(s) * o2 * o2 * o2;   // > 0
            int pos = atomicAdd(&s_n, 1);
            if (pos < MAXC) {
                s_key[pos] = ((unsigned long long)__float_as_uint(v) << 32) |
                             (unsigned)(0x7FFFFFFF - a);
                s_ovs[pos] = ov;
                s_ia[pos]  = a;
            }
        }
    }
    __syncthreads();

    int n = min(s_n, MAXC);

    // parallel rank-select with early exit: keys distinct, winner iff rank<10.
    // Once rank >= KTOP the candidate is provably a loser -> break (exact).
    for (int c = tid; c < n; c += 128) {
        unsigned long long key = s_key[c];
        int rank = 0;
        if (n > KTOP) {
            for (int j = 0; j < n; j++) {
                rank += (s_key[j] > key);
                if (rank >= KTOP) break;
            }
        }
        if (rank < KTOP) {
            int a = s_ia[c];
            size_t i = (size_t)b * NA + a;
            atomicAdd(&g_cnt[i], 1);
            g_m[i]  = bm & 63;
            g_al[i] = __uint_as_float((unsigned)(key >> 32));
            g_ov[i] = s_ovs[c];
        }
    }

    // fillers when n < KTOP: smallest global anchor indices not positive
    if (n < KTOP && tid < n + KTOP) {
        bool inPos = false; int less = 0;
        for (int j = 0; j < n; j++) {
            int ia = s_ia[j];
            inPos |= (ia == tid);
            less  += (ia < tid);
        }
        if (!inPos && (tid - less) < (KTOP - n)) {
            float2 an = __ldg((const float2*)anc + tid);
            if (inside_box(an, g)) {
                size_t i = (size_t)b * NA + tid;
                atomicAdd(&g_cnt[i], 1);
                g_m[i]  = bm & 63;
                g_al[i] = 0.0f;
                float4 p = __ldg(pb + tid);
                g_ov[i] = fmaxf(ciou_f(g, p), 0.0f);
            }
        }
    }
}

// ---------------- K2: resolve assignment (warp-cooperative multi) ---------
__global__ void __launch_bounds__(256) k_phaseB(
    const float* __restrict__ pd_scores, const float* __restrict__ pd_bboxes,
    const float* __restrict__ anc, const int* __restrict__ gt_labels,
    const float* __restrict__ gt_bboxes)
{
    int b    = blockIdx.y;
    int a    = blockIdx.x * 256 + threadIdx.x;
    int lane = threadIdx.x & 31;
    bool valid = a < NA;
    size_t i = (size_t)b * NA + (valid ? a : 0);

    int   cnt = 0, tgt = 0;
    float al = 0.0f, ov = 0.0f;
    if (valid) {
        cnt = __ldg(&g_cnt[i]);
        tgt = __ldg(&g_m[i]);
        al  = __ldg(&g_al[i]);
        ov  = __ldg(&g_ov[i]);
    }

    bool multi = valid && (cnt > 1);
    // multi lanes preload their anchor data for the shfl broadcast
    float2 an_m = make_float2(0.f, 0.f);
    float4 p_m  = make_float4(0.f, 0.f, 0.f, 0.f);
    if (multi) {
        an_m = __ldg((const float2*)anc + a);
        p_m  = __ldg((const float4*)pd_bboxes + (size_t)b * NA + a);
    }

    const float4* gb = (const float4*)gt_bboxes + b * NM;
    unsigned mmask = __ballot_sync(0xffffffffu, multi);
    while (mmask) {
        int src = __ffs(mmask) - 1;
        mmask &= mmask - 1;
        float anx = __shfl_sync(0xffffffffu, an_m.x, src);
        float any = __shfl_sync(0xffffffffu, an_m.y, src);
        float px  = __shfl_sync(0xffffffffu, p_m.x, src);
        float py  = __shfl_sync(0xffffffffu, p_m.y, src);
        float pz  = __shfl_sync(0xffffffffu, p_m.z, src);
        float pw  = __shfl_sync(0xffffffffu, p_m.w, src);
        float2 an = make_float2(anx, any);
        float4 p  = make_float4(px, py, pz, pw);

        // 2 gts per lane: m = lane, lane+32 (ascending within lane)
        float best = -1.0f; int bmx = 0;
#pragma unroll
        for (int s = 0; s < 2; s++) {
            int m = lane + s * 32;
            float4 gg = __ldg(gb + m);
            float ovm = inside_box(an, gg) ? fmaxf(ciou_f(gg, p), 0.0f) : 0.0f;
            if (ovm > best) { best = ovm; bmx = m; }
        }
        // warp argmax with lowest-m tie-break
#pragma unroll
        for (int o = 16; o > 0; o >>= 1) {
            float ov2 = __shfl_down_sync(0xffffffffu, best, o);
            int   m2  = __shfl_down_sync(0xffffffffu, bmx,  o);
            if (ov2 > best || (ov2 == best && m2 < bmx)) { best = ov2; bmx = m2; }
        }
        float rbest = __shfl_sync(0xffffffffu, best, 0);
        int   rbmx  = __shfl_sync(0xffffffffu, bmx,  0);
        if (lane == src) { tgt = rbmx; ov = rbest; }
    }

    if (multi) {
        float4 gg = __ldg(gb + tgt);
        if (inside_box(an_m, gg) && ov > 0.0f) {
            int lb = __ldg(gt_labels + b * NM + tgt);
            float s = pd_scores[(size_t)b * NA * NC + (size_t)a * NC + lb];
            float o2 = ov * ov;
            al = sqrtf(s) * o2 * o2 * o2;
        } else {
            al = 0.0f;
        }
    }

    if (!valid) return;

    if (cnt == 0) {
        g_lbl[i] = -1; g_tgt[i] = 0; g_fin[i] = 0.0f;
        return;
    }
    g_lbl[i] = __ldg(gt_labels + b * NM + tgt);
    g_tgt[i] = tgt;
    g_fin[i] = al;
    atomicMax(&g_pos_al[b * NM + tgt], __float_as_uint(al));
    atomicMax(&g_pos_ov[b * NM + tgt], __float_as_uint(ov));
}

// ---------------- K3: all outputs (warp-autonomous, 256-bit stores) -------
__global__ void __launch_bounds__(256) k_phaseC(
    const float* __restrict__ gt_bboxes, float* __restrict__ out)
{
    int b    = blockIdx.y;
    int lane = threadIdx.x & 31;
    int w    = threadIdx.x >> 5;
    int arow = blockIdx.x * 128 + w * 16;    // this warp's 16 anchors

    const size_t N = (size_t)BSZ * NA;

    float norm = 0.0f; int lbl = -1;
    int a = arow + lane;
    if (lane < 16 && a < NA) {
        size_t i = (size_t)b * NA + a;
        lbl     = __ldg(&g_lbl[i]);
        int tgt = __ldg(&g_tgt[i]);
        int fg  = lbl >= 0;

        float4 box = __ldg((const float4*)gt_bboxes + b * NM + tgt);
        out[i] = fg ? (float)lbl : (float)NC;               // labels
        ((float4*)(out + N))[i] = box;                      // bboxes
        out[N * (size_t)85 + i] = fg ? 1.0f : 0.0f;         // fg
        out[N * (size_t)86 + i] = (float)tgt;               // gt_idx

        if (fg) {
            float pa = __uint_as_float(__ldg(&g_pos_al[b * NM + tgt]));
            float po = __uint_as_float(__ldg(&g_pos_ov[b * NM + tgt]));
            norm = __ldg(&g_fin[i]) * po / (pa + EPS9);
        }
    }

    float* basep = out + N * 5 + ((size_t)b * NA + arow) * NC;
#pragma unroll
    for (int r = 0; r < 5; r++) {
        int idx = r * 32 + lane;              // 0..159
        int row = idx / (NC / 8);             // 0..15 (source lane)
        int k   = idx - row * (NC / 8);       // 8-class chunk within row
        float nv = __shfl_sync(0xffffffffu, norm, row);
        int   lb = __shfl_sync(0xffffffffu, lbl,  row);
        if (arow + row < NA) {
            float v[8];
#pragma unroll
            for (int j = 0; j < 8; j++)
                v[j] = ((lb >> 3) == k && (lb & 7) == j) ? nv : 0.0f;
            float* ptr = basep + (size_t)row * NC + k * 8;
            asm volatile(
                "st.global.v8.f32 [%0], {%1, %2, %3, %4, %5, %6, %7, %8};"
                :: "l"(ptr), "f"(v[0]), "f"(v[1]), "f"(v[2]), "f"(v[3]),
                   "f"(v[4]), "f"(v[5]), "f"(v[6]), "f"(v[7])
                : "memory");
        }
    }
}

// ---------------- launcher ----------------
extern "C" void kernel_launch(void* const* d_in, const int* in_sizes, int n_in,
                              void* d_out, int out_size)
{
    const float* pd_scores = (const float*)d_in[0];
    const float* pd_bboxes = (const float*)d_in[1];
    const float* anc       = (const float*)d_in[2];
    const int*   gt_labels = (const int*)  d_in[3];
    const float* gt_bboxes = (const float*)d_in[4];
    float* out = (float*)d_out;

    (void)in_sizes; (void)n_in; (void)out_size;

    k_prep<<<ZBLK + 1, 256>>>(anc);

    k_phaseA<<<BSZ * NM, 128>>>(pd_scores, pd_bboxes, anc, gt_labels, gt_bboxes);

    dim3 gB((NA + 255) / 256, BSZ);
    k_phaseB<<<gB, 256>>>(pd_scores, pd_bboxes, anc, gt_labels, gt_bboxes);

    dim3 gC((NA + 127) / 128, BSZ);
    k_phaseC<<<gC, 256>>>(gt_bboxes, out);
}

// round 15
// speedup vs baseline: 1.3219x; 1.3219x over previous
#include <cuda_runtime.h>
#include <math.h>
#include <stdint.h>

#define BSZ 16
#define NA  8400
#define NM  64
#define NC  80
#define KTOP 10
#define EPS9 1e-9f

#define NBX   16
#define NBINS 256          // 16x16 bins of 40px over 640x640
#define INV_BINW 0.025f    // 1/40
#define MAXC  1024

#define ZBLK 525           // blocks that init scratch (g_cnt etc.)

// ---------------- scratch (__device__ globals; allowed) ----------------
__device__ int      g_cnt[BSZ * NA];
__device__ int      g_m[BSZ * NA];
__device__ float    g_al[BSZ * NA];
__device__ float    g_ov[BSZ * NA];
__device__ int      g_lbl[BSZ * NA];     // final label, -1 = background
__device__ int      g_tgt[BSZ * NA];
__device__ float    g_fin[BSZ * NA];
__device__ unsigned g_pos_al[BSZ * NM];
__device__ unsigned g_pos_ov[BSZ * NM];
// binning
__device__ float2   g_bxy[NA];
__device__ int      g_bidx[NA];
__device__ int      g_bs[NBINS + 1];

// ---------------- helpers ----------------
static __device__ __forceinline__ float ciou_f(float4 g, float4 p) {
    const float eps = 1e-7f;
    float w1 = g.z - g.x, h1 = g.w - g.y;
    float w2 = p.z - p.x, h2 = p.w - p.y;
    float iw = fmaxf(fminf(g.z, p.z) - fmaxf(g.x, p.x), 0.0f);
    float ih = fmaxf(fminf(g.w, p.w) - fmaxf(g.y, p.y), 0.0f);
    float inter = iw * ih;
    float uni = w1 * h1 + w2 * h2 - inter + eps;
    float iou = inter / uni;
    float cw = fmaxf(g.z, p.z) - fminf(g.x, p.x);
    float ch = fmaxf(g.w, p.w) - fminf(g.y, p.y);
    float c2 = cw * cw + ch * ch + eps;
    float dx = p.x + p.z - g.x - g.z;
    float dy = p.y + p.w - g.y - g.w;
    float rho2 = (dx * dx + dy * dy) * 0.25f;
    float d = atanf(w1 / (h1 + eps)) - atanf(w2 / (h2 + eps));
    float v = 0.4052847345693511f * d * d;   // 4/pi^2
    float alpha = v / (v - iou + 1.0f + eps);
    return iou - (rho2 / c2 + v * alpha);
}

static __device__ __forceinline__ bool inside_box(float2 a, float4 g) {
    float m0 = fminf(a.x - g.x, a.y - g.y);
    float m1 = fminf(g.z - a.x, g.w - a.y);
    return fminf(m0, m1) > EPS9;
}

// ---------------- K0: init scratch + bin anchors (fused, small) -----------
__global__ void __launch_bounds__(256) k_prep(const float* __restrict__ anc) {
    int tid = threadIdx.x;

    if (blockIdx.x == ZBLK) {
        __shared__ int cnt[NBINS];
        __shared__ int ofs[NBINS];
        __shared__ int scn[NBINS];
        cnt[tid] = 0;
        __syncthreads();
        for (int a = tid; a < NA; a += 256) {
            float2 an = ((const float2*)anc)[a];
            int bx = min(max((int)(an.x * INV_BINW), 0), NBX - 1);
            int by = min(max((int)(an.y * INV_BINW), 0), NBX - 1);
            atomicAdd(&cnt[by * NBX + bx], 1);
        }
        __syncthreads();
        int x = cnt[tid];
        scn[tid] = x;
        __syncthreads();
#pragma unroll
        for (int d = 1; d < NBINS; d <<= 1) {
            int v = (tid >= d) ? scn[tid - d] : 0;
            __syncthreads();
            scn[tid] += v;
            __syncthreads();
        }
        int excl = scn[tid] - x;
        ofs[tid] = excl;
        g_bs[tid] = excl;
        if (tid == NBINS - 1) g_bs[NBINS] = scn[tid];
        __syncthreads();
        for (int a = tid; a < NA; a += 256) {
            float2 an = ((const float2*)anc)[a];
            int bx = min(max((int)(an.x * INV_BINW), 0), NBX - 1);
            int by = min(max((int)(an.y * INV_BINW), 0), NBX - 1);
            int p = atomicAdd(&ofs[by * NBX + bx], 1);
            g_bxy[p] = an;
            g_bidx[p] = a;
        }
        return;
    }

    int t = blockIdx.x * 256 + tid;
    if (t < BSZ * NA) g_cnt[t] = 0;
    if (t < BSZ * NM) { g_pos_al[t] = 0u; g_pos_ov[t] = 0u; }
}

// ---------------- K1: per (b,m) binned scan + parallel rank top-10 --------
__global__ void __launch_bounds__(128) k_phaseA(
    const float* __restrict__ pd_scores, const float* __restrict__ pd_bboxes,
    const float* __restrict__ anc, const int* __restrict__ gt_labels,
    const float* __restrict__ gt_bboxes)
{
    int bm = blockIdx.x;
    int b = bm >> 6;
    int tid = threadIdx.x;

    __shared__ unsigned long long s_key[MAXC];  // (vbits<<32)|(0x7FFFFFFF - idx)
    __shared__ float s_ovs[MAXC];
    __shared__ int   s_ia[MAXC];
    __shared__ int   s_n;
    if (tid == 0) s_n = 0;

    float4 g = __ldg((const float4*)gt_bboxes + bm);
    int lbl = __ldg(gt_labels + bm);
    const float* sc = pd_scores + (size_t)b * NA * NC + lbl;
    const float4* pb = (const float4*)pd_bboxes + (size_t)b * NA;
    __syncthreads();

    int bx0 = min(max((int)(g.x * INV_BINW), 0), NBX - 1);
    int bx1 = min(max((int)(g.z * INV_BINW), 0), NBX - 1);
    int by0 = min(max((int)(g.y * INV_BINW), 0), NBX - 1);
    int by1 = min(max((int)(g.w * INV_BINW), 0), NBX - 1);

    for (int by = by0; by <= by1; by++) {
        int j0 = g_bs[by * NBX + bx0];
        int j1 = g_bs[by * NBX + bx1 + 1];
        for (int j = j0 + tid; j < j1; j += 128) {
            float2 an = g_bxy[j];
            if (!inside_box(an, g)) continue;
            int a = g_bidx[j];
            // issue BOTH loads before the ciou math (independent; breaks the
            // load->math->load dependent chain)
            float4 p = __ldg(pb + a);
            float s  = __ldg(sc + (size_t)a * NC);
            float ov = fmaxf(ciou_f(g, p), 0.0f);
            if (ov <= 0.0f) continue;
            float o2 = ov * ov;
            float v = sqrtf(s) * o2 * o2 * o2;   // > 0
            int pos = atomicAdd(&s_n, 1);
            if (pos < MAXC) {
                s_key[pos] = ((unsigned long long)__float_as_uint(v) << 32) |
                             (unsigned)(0x7FFFFFFF - a);
                s_ovs[pos] = ov;
                s_ia[pos]  = a;
            }
        }
    }
    __syncthreads();

    int n = min(s_n, MAXC);

    // parallel rank-select: keys distinct, winner iff rank < KTOP.
    // If n <= KTOP every candidate wins (rank trivially < KTOP).
    for (int c = tid; c < n; c += 128) {
        unsigned long long key = s_key[c];
        int rank = 0;
        if (n > KTOP)
            for (int j = 0; j < n; j++) rank += (s_key[j] > key);
        if (rank < KTOP) {
            int a = s_ia[c];
            size_t i = (size_t)b * NA + a;
            atomicAdd(&g_cnt[i], 1);
            g_m[i]  = bm & 63;
            g_al[i] = __uint_as_float((unsigned)(key >> 32));
            g_ov[i] = s_ovs[c];
        }
    }

    // fillers when n < KTOP: smallest global anchor indices not positive
    if (n < KTOP && tid < n + KTOP) {
        bool inPos = false; int less = 0;
        for (int j = 0; j < n; j++) {
            int ia = s_ia[j];
            inPos |= (ia == tid);
            less  += (ia < tid);
        }
        if (!inPos && (tid - less) < (KTOP - n)) {
            float2 an = __ldg((const float2*)anc + tid);
            if (inside_box(an, g)) {
                size_t i = (size_t)b * NA + tid;
                atomicAdd(&g_cnt[i], 1);
                g_m[i]  = bm & 63;
                g_al[i] = 0.0f;
                float4 p = __ldg(pb + tid);
                g_ov[i] = fmaxf(ciou_f(g, p), 0.0f);
            }
        }
    }
}

// ---------------- K2: resolve assignment + scalar outputs -----------------
__global__ void __launch_bounds__(256) k_phaseB(
    const float* __restrict__ pd_scores, const float* __restrict__ pd_bboxes,
    const float* __restrict__ anc, const int* __restrict__ gt_labels,
    const float* __restrict__ gt_bboxes, float* __restrict__ out)
{
    int b = blockIdx.y;
    int a = blockIdx.x * 256 + threadIdx.x;
    if (a >= NA) return;
    size_t i = (size_t)b * NA + a;
    const size_t N = (size_t)BSZ * NA;

    int   cnt = __ldg(&g_cnt[i]);
    int   tgt = __ldg(&g_m[i]);
    float al  = __ldg(&g_al[i]);
    float ov  = __ldg(&g_ov[i]);

    if (cnt == 0) {
        g_lbl[i] = -1; g_tgt[i] = 0; g_fin[i] = 0.0f;
        float4 box = __ldg((const float4*)gt_bboxes + b * NM);
        out[i] = (float)NC;                                 // labels
        ((float4*)(out + N))[i] = box;                      // bboxes
        out[N * (size_t)85 + i] = 0.0f;                     // fg
        out[N * (size_t)86 + i] = 0.0f;                     // gt_idx
        return;
    }

    if (cnt > 1) {
        // multi-assigned: argmax over m of overlaps (ties -> lowest m)
        float2 an = __ldg((const float2*)anc + a);
        float4 p  = __ldg((const float4*)pd_bboxes + (size_t)b * NA + a);
        const float4* gb = (const float4*)gt_bboxes + b * NM;
        float best = -1.0f; int bmx = 0;
#pragma unroll 4
        for (int m = 0; m < NM; m++) {
            float4 gg = __ldg(gb + m);
            float ovm = inside_box(an, gg) ? fmaxf(ciou_f(gg, p), 0.0f) : 0.0f;
            if (ovm > best) { best = ovm; bmx = m; }
        }
        tgt = bmx; ov = best;
        float4 gg = __ldg(gb + tgt);
        if (inside_box(an, gg) && ov > 0.0f) {
            int lb = __ldg(gt_labels + b * NM + tgt);
            float s = pd_scores[(size_t)b * NA * NC + (size_t)a * NC + lb];
            float o2 = ov * ov;
            al = sqrtf(s) * o2 * o2 * o2;
        } else {
            al = 0.0f;
        }
    }

    int lb = __ldg(gt_labels + b * NM + tgt);
    g_lbl[i] = lb;
    g_tgt[i] = tgt;
    g_fin[i] = al;
    atomicMax(&g_pos_al[b * NM + tgt], __float_as_uint(al));
    atomicMax(&g_pos_ov[b * NM + tgt], __float_as_uint(ov));

    float4 box = __ldg((const float4*)gt_bboxes + b * NM + tgt);
    out[i] = (float)lb;                                     // labels
    ((float4*)(out + N))[i] = box;                          // bboxes
    out[N * (size_t)85 + i] = 1.0f;                         // fg
    out[N * (size_t)86 + i] = (float)tgt;                   // gt_idx
}

// ---------------- K3: score rows only (warp-autonomous, 256-bit stores) ---
__global__ void __launch_bounds__(256) k_phaseC(float* __restrict__ out)
{
    int b    = blockIdx.y;
    int lane = threadIdx.x & 31;
    int w    = threadIdx.x >> 5;
    int arow = blockIdx.x * 128 + w * 16;    // this warp's 16 anchors

    const size_t N = (size_t)BSZ * NA;

    float norm = 0.0f; int lbl = -1;
    int a = arow + lane;
    if (lane < 16 && a < NA) {
        size_t i = (size_t)b * NA + a;
        lbl = __ldg(&g_lbl[i]);
        if (lbl >= 0) {
            int tgt = __ldg(&g_tgt[i]);
            float pa = __uint_as_float(__ldg(&g_pos_al[b * NM + tgt]));
            float po = __uint_as_float(__ldg(&g_pos_ov[b * NM + tgt]));
            norm = __ldg(&g_fin[i]) * po / (pa + EPS9);
        }
    }

    float* basep = out + N * 5 + ((size_t)b * NA + arow) * NC;
#pragma unroll
    for (int r = 0; r < 5; r++) {
        int idx = r * 32 + lane;              // 0..159
        int row = idx / (NC / 8);             // 0..15 (source lane)
        int k   = idx - row * (NC / 8);       // 8-class chunk within row
        float nv = __shfl_sync(0xffffffffu, norm, row);
        int   lb = __shfl_sync(0xffffffffu, lbl,  row);
        if (arow + row < NA) {
            float v[8];
#pragma unroll
            for (int j = 0; j < 8; j++)
                v[j] = ((lb >> 3) == k && (lb & 7) == j) ? nv : 0.0f;
            float* ptr = basep + (size_t)row * NC + k * 8;
            asm volatile(
                "st.global.v8.f32 [%0], {%1, %2, %3, %4, %5, %6, %7, %8};"
                :: "l"(ptr), "f"(v[0]), "f"(v[1]), "f"(v[2]), "f"(v[3]),
                   "f"(v[4]), "f"(v[5]), "f"(v[6]), "f"(v[7])
                : "memory");
        }
    }
}

// ---------------- launcher ----------------
extern "C" void kernel_launch(void* const* d_in, const int* in_sizes, int n_in,
                              void* d_out, int out_size)
{
    const float* pd_scores = (const float*)d_in[0];
    const float* pd_bboxes = (const float*)d_in[1];
    const float* anc       = (const float*)d_in[2];
    const int*   gt_labels = (const int*)  d_in[3];
    const float* gt_bboxes = (const float*)d_in[4];
    float* out = (float*)d_out;

    (void)in_sizes; (void)n_in; (void)out_size;

    k_prep<<<ZBLK + 1, 256>>>(anc);

    k_phaseA<<<BSZ * NM, 128>>>(pd_scores, pd_bboxes, anc, gt_labels, gt_bboxes);

    dim3 gB((NA + 255) / 256, BSZ);
    k_phaseB<<<gB, 256>>>(pd_scores, pd_bboxes, anc, gt_labels, gt_bboxes, out);

    dim3 gC((NA + 127) / 128, BSZ);
    k_phaseC<<<gC, 256>>>(out);
}

// round 17
// speedup vs baseline: 1.3271x; 1.0039x over previous
#include <cuda_runtime.h>
#include <math.h>
#include <stdint.h>

#define BSZ 16
#define NA  8400
#define NM  64
#define NC  80
#define KTOP 10
#define EPS9 1e-9f

#define NBX   16
#define NBINS 256          // 16x16 bins of 40px over 640x640
#define INV_BINW 0.025f    // 1/40
#define MAXC  1024

// ---------------- scratch (__device__ globals; zero-initialized) ----------
__device__ int      g_cnt[BSZ * NA];     // zero at entry (initial + phaseB clean)
__device__ int      g_m[BSZ * NA];
__device__ float    g_al[BSZ * NA];
__device__ float    g_ov[BSZ * NA];
__device__ int      g_lbl[BSZ * NA];     // final label, -1 = background
__device__ int      g_tgt[BSZ * NA];
__device__ float    g_fin[BSZ * NA];
__device__ unsigned g_pos_al[BSZ * NM];  // zeroed by phaseA block bm each launch
__device__ unsigned g_pos_ov[BSZ * NM];
// binning
__device__ float2   g_bxy[NA];
__device__ int      g_bidx[NA];
__device__ int      g_bs[NBINS + 1];

// ---------------- helpers ----------------
static __device__ __forceinline__ float ciou_f(float4 g, float4 p) {
    const float eps = 1e-7f;
    float w1 = g.z - g.x, h1 = g.w - g.y;
    float w2 = p.z - p.x, h2 = p.w - p.y;
    float iw = fmaxf(fminf(g.z, p.z) - fmaxf(g.x, p.x), 0.0f);
    float ih = fmaxf(fminf(g.w, p.w) - fmaxf(g.y, p.y), 0.0f);
    float inter = iw * ih;
    float uni = w1 * h1 + w2 * h2 - inter + eps;
    float iou = inter / uni;
    float cw = fmaxf(g.z, p.z) - fminf(g.x, p.x);
    float ch = fmaxf(g.w, p.w) - fminf(g.y, p.y);
    float c2 = cw * cw + ch * ch + eps;
    float dx = p.x + p.z - g.x - g.z;
    float dy = p.y + p.w - g.y - g.w;
    float rho2 = (dx * dx + dy * dy) * 0.25f;
    float d = atanf(w1 / (h1 + eps)) - atanf(w2 / (h2 + eps));
    float v = 0.4052847345693511f * d * d;   // 4/pi^2
    float alpha = v / (v - iou + 1.0f + eps);
    return iou - (rho2 / c2 + v * alpha);
}

static __device__ __forceinline__ bool inside_box(float2 a, float4 g) {
    float m0 = fminf(a.x - g.x, a.y - g.y);
    float m1 = fminf(g.z - a.x, g.w - a.y);
    return fminf(m0, m1) > EPS9;
}

// ---------------- K0: bin anchors (single block) --------------------------
__global__ void __launch_bounds__(256) k_bin(const float* __restrict__ anc) {
    __shared__ int cnt[NBINS];
    __shared__ int ofs[NBINS];
    __shared__ int scn[NBINS];
    int tid = threadIdx.x;
    cnt[tid] = 0;
    __syncthreads();
    for (int a = tid; a < NA; a += 256) {
        float2 an = ((const float2*)anc)[a];
        int bx = min(max((int)(an.x * INV_BINW), 0), NBX - 1);
        int by = min(max((int)(an.y * INV_BINW), 0), NBX - 1);
        atomicAdd(&cnt[by * NBX + bx], 1);
    }
    __syncthreads();
    int x = cnt[tid];
    scn[tid] = x;
    __syncthreads();
#pragma unroll
    for (int d = 1; d < NBINS; d <<= 1) {
        int v = (tid >= d) ? scn[tid - d] : 0;
        __syncthreads();
        scn[tid] += v;
        __syncthreads();
    }
    int excl = scn[tid] - x;
    ofs[tid] = excl;
    g_bs[tid] = excl;
    if (tid == NBINS - 1) g_bs[NBINS] = scn[tid];
    __syncthreads();
    for (int a = tid; a < NA; a += 256) {
        float2 an = ((const float2*)anc)[a];
        int bx = min(max((int)(an.x * INV_BINW), 0), NBX - 1);
        int by = min(max((int)(an.y * INV_BINW), 0), NBX - 1);
        int p = atomicAdd(&ofs[by * NBX + bx], 1);
        g_bxy[p] = an;
        g_bidx[p] = a;
    }
}

// ---------------- K1: per (b,m) binned scan + parallel rank top-10 --------
__global__ void __launch_bounds__(128) k_phaseA(
    const float* __restrict__ pd_scores, const float* __restrict__ pd_bboxes,
    const float* __restrict__ anc, const int* __restrict__ gt_labels,
    const float* __restrict__ gt_bboxes)
{
    int bm = blockIdx.x;
    int b = bm >> 6;
    int tid = threadIdx.x;

    __shared__ unsigned long long s_key[MAXC];  // (vbits<<32)|(0x7FFFFFFF - idx)
    __shared__ float s_ovs[MAXC];
    __shared__ int   s_ia[MAXC];
    __shared__ int   s_n;
    if (tid == 0) {
        s_n = 0;
        g_pos_al[bm] = 0u;        // safe: prior replay's phaseC already read
        g_pos_ov[bm] = 0u;
    }

    float4 g = __ldg((const float4*)gt_bboxes + bm);
    int lbl = __ldg(gt_labels + bm);
    const float* sc = pd_scores + (size_t)b * NA * NC + lbl;
    const float4* pb = (const float4*)pd_bboxes + (size_t)b * NA;
    __syncthreads();

    int bx0 = min(max((int)(g.x * INV_BINW), 0), NBX - 1);
    int bx1 = min(max((int)(g.z * INV_BINW), 0), NBX - 1);
    int by0 = min(max((int)(g.y * INV_BINW), 0), NBX - 1);
    int by1 = min(max((int)(g.w * INV_BINW), 0), NBX - 1);

    for (int by = by0; by <= by1; by++) {
        int j0 = g_bs[by * NBX + bx0];
        int j1 = g_bs[by * NBX + bx1 + 1];
        for (int j = j0 + tid; j < j1; j += 128) {
            float2 an = g_bxy[j];
            if (!inside_box(an, g)) continue;
            int a = g_bidx[j];
            // issue BOTH loads before the ciou math (independent)
            float4 p = __ldg(pb + a);
            float s  = __ldg(sc + (size_t)a * NC);
            float ov = fmaxf(ciou_f(g, p), 0.0f);
            if (ov <= 0.0f) continue;
            float o2 = ov * ov;
            float v = sqrtf(s) * o2 * o2 * o2;   // > 0
            int pos = atomicAdd(&s_n, 1);
            if (pos < MAXC) {
                s_key[pos] = ((unsigned long long)__float_as_uint(v) << 32) |
                             (unsigned)(0x7FFFFFFF - a);
                s_ovs[pos] = ov;
                s_ia[pos]  = a;
            }
        }
    }
    __syncthreads();

    int n = min(s_n, MAXC);

    // parallel rank-select: keys distinct, winner iff rank < KTOP
    for (int c = tid; c < n; c += 128) {
        unsigned long long key = s_key[c];
        int rank = 0;
        if (n > KTOP)
            for (int j = 0; j < n; j++) rank += (s_key[j] > key);
        if (rank < KTOP) {
            int a = s_ia[c];
            size_t i = (size_t)b * NA + a;
            atomicAdd(&g_cnt[i], 1);
            g_m[i]  = bm & 63;
            g_al[i] = __uint_as_float((unsigned)(key >> 32));
            g_ov[i] = s_ovs[c];
        }
    }

    // fillers when n < KTOP: smallest global anchor indices not positive
    if (n < KTOP && tid < n + KTOP) {
        bool inPos = false; int less = 0;
        for (int j = 0; j < n; j++) {
            int ia = s_ia[j];
            inPos |= (ia == tid);
            less  += (ia < tid);
        }
        if (!inPos && (tid - less) < (KTOP - n)) {
            float2 an = __ldg((const float2*)anc + tid);
            if (inside_box(an, g)) {
                size_t i = (size_t)b * NA + tid;
                atomicAdd(&g_cnt[i], 1);
                g_m[i]  = bm & 63;
                g_al[i] = 0.0f;
                float4 p = __ldg(pb + tid);
                g_ov[i] = fmaxf(ciou_f(g, p), 0.0f);
            }
        }
    }
}

// ---------------- K2: resolve assignment + scalar outputs -----------------
__global__ void __launch_bounds__(256) k_phaseB(
    const float* __restrict__ pd_scores, const float* __restrict__ pd_bboxes,
    const float* __restrict__ anc, const int* __restrict__ gt_labels,
    const float* __restrict__ gt_bboxes, float* __restrict__ out)
{
    int b = blockIdx.y;
    int a = blockIdx.x * 256 + threadIdx.x;
    if (a >= NA) return;
    size_t i = (size_t)b * NA + a;
    const size_t N = (size_t)BSZ * NA;

    int   cnt = __ldg(&g_cnt[i]);
    int   tgt = __ldg(&g_m[i]);
    float al  = __ldg(&g_al[i]);
    float ov  = __ldg(&g_ov[i]);

    if (cnt == 0) {
        g_lbl[i] = -1; g_tgt[i] = 0; g_fin[i] = 0.0f;
        float4 box = __ldg((const float4*)gt_bboxes + b * NM);
        out[i] = (float)NC;                                 // labels
        ((float4*)(out + N))[i] = box;                      // bboxes
        out[N * (size_t)85 + i] = 0.0f;                     // fg
        out[N * (size_t)86 + i] = 0.0f;                     // gt_idx
        return;
    }
    g_cnt[i] = 0;                        // self-clean for next launch

    if (cnt > 1) {
        // multi-assigned: argmax over m of overlaps (ties -> lowest m)
        float2 an = __ldg((const float2*)anc + a);
        float4 p  = __ldg((const float4*)pd_bboxes + (size_t)b * NA + a);
        const float4* gb = (const float4*)gt_bboxes + b * NM;
        float best = -1.0f; int bmx = 0;
#pragma unroll 4
        for (int m = 0; m < NM; m++) {
            float4 gg = __ldg(gb + m);
            float ovm = inside_box(an, gg) ? fmaxf(ciou_f(gg, p), 0.0f) : 0.0f;
            if (ovm > best) { best = ovm; bmx = m; }
        }
        tgt = bmx; ov = best;
        float4 gg = __ldg(gb + tgt);
        if (inside_box(an, gg) && ov > 0.0f) {
            int lb = __ldg(gt_labels + b * NM + tgt);
            float s = pd_scores[(size_t)b * NA * NC + (size_t)a * NC + lb];
            float o2 = ov * ov;
            al = sqrtf(s) * o2 * o2 * o2;
        } else {
            al = 0.0f;
        }
    }

    int lb = __ldg(gt_labels + b * NM + tgt);
    g_lbl[i] = lb;
    g_tgt[i] = tgt;
    g_fin[i] = al;
    atomicMax(&g_pos_al[b * NM + tgt], __float_as_uint(al));
    atomicMax(&g_pos_ov[b * NM + tgt], __float_as_uint(ov));

    float4 box = __ldg((const float4*)gt_bboxes + b * NM + tgt);
    out[i] = (float)lb;                                     // labels
    ((float4*)(out + N))[i] = box;                          // bboxes
    out[N * (size_t)85 + i] = 1.0f;                         // fg
    out[N * (size_t)86 + i] = (float)tgt;                   // gt_idx
}

// ---------------- K3: score rows (zero-register fast path) ----------------
// Steady state: store a persistent all-zero v8 block. Only the rare hot
// chunk ((lb>>3)==k on an fg anchor) briefly patches the registers.
__global__ void __launch_bounds__(256) k_phaseC(float* __restrict__ out)
{
    int b    = blockIdx.y;
    int lane = threadIdx.x & 31;
    int w    = threadIdx.x >> 5;
    int arow = blockIdx.x * 128 + w * 16;    // this warp's 16 anchors

    const size_t N = (size_t)BSZ * NA;

    float norm = 0.0f; int lbl = -1;
    int a = arow + lane;
    if (lane < 16 && a < NA) {
        size_t i = (size_t)b * NA + a;
        lbl = __ldg(&g_lbl[i]);
        if (lbl >= 0) {
            int tgt = __ldg(&g_tgt[i]);
            float pa = __uint_as_float(__ldg(&g_pos_al[b * NM + tgt]));
            float po = __uint_as_float(__ldg(&g_pos_ov[b * NM + tgt]));
            norm = __ldg(&g_fin[i]) * po / (pa + EPS9);
        }
    }

    float v[8];
#pragma unroll
    for (int j = 0; j < 8; j++) v[j] = 0.0f;

    float* basep = out + N * 5 + ((size_t)b * NA + arow) * NC;
#pragma unroll
    for (int r = 0; r < 5; r++) {
        int idx = r * 32 + lane;              // 0..159
        int row = idx / (NC / 8);             // 0..15 (source lane)
        int k   = idx - row * (NC / 8);       // 8-class chunk within row
        float nv = __shfl_sync(0xffffffffu, norm, row);
        int   lb = __shfl_sync(0xffffffffu, lbl,  row);
        if (arow + row < NA) {
            bool hot = ((lb >> 3) == k);      // lb = -1 -> never hot
            if (hot) {
                int l4 = lb & 7;
#pragma unroll
                for (int j = 0; j < 8; j++) if (l4 == j) v[j] = nv;
            }
            float* ptr = basep + (size_t)row * NC + k * 8;
            asm volatile(
                "st.global.v8.f32 [%0], {%1, %2, %3, %4, %5, %6, %7, %8};"
                :: "l"(ptr), "f"(v[0]), "f"(v[1]), "f"(v[2]), "f"(v[3]),
                   "f"(v[4]), "f"(v[5]), "f"(v[6]), "f"(v[7])
                : "memory");
            if (hot) {
#pragma unroll
                for (int j = 0; j < 8; j++) v[j] = 0.0f;
            }
        }
    }
}

// ---------------- launcher ----------------
extern "C" void kernel_launch(void* const* d_in, const int* in_sizes, int n_in,
                              void* d_out, int out_size)
{
    const float* pd_scores = (const float*)d_in[0];
    const float* pd_bboxes = (const float*)d_in[1];
    const float* anc       = (const float*)d_in[2];
    const int*   gt_labels = (const int*)  d_in[3];
    const float* gt_bboxes = (const float*)d_in[4];
    float* out = (float*)d_out;

    (void)in_sizes; (void)n_in; (void)out_size;

    k_bin<<<1, 256>>>(anc);

    k_phaseA<<<BSZ * NM, 128>>>(pd_scores, pd_bboxes, anc, gt_labels, gt_bboxes);

    dim3 gB((NA + 255) / 256, BSZ);
    k_phaseB<<<gB, 256>>>(pd_scores, pd_bboxes, anc, gt_labels, gt_bboxes, out);

    dim3 gC((NA + 127) / 128, BSZ);
    k_phaseC<<<gC, 256>>>(out);
}